// round 13
// baseline (speedup 1.0000x reference)
#include <cuda_runtime.h>

#define NN 50000
#define NE 800000
#define ET (NE + NN)
#define NC 64
#define NCHUNK ((NN + 1023) / 1024)
#define NBIN 64

// ---------------------------------------------------------------------------
// Static device scratch (allocation-free rule).
// ---------------------------------------------------------------------------
__device__ float g_hA[NN * NC];
__device__ float g_hB[NN * NC];
__device__ float2 g_PA[NN];           // per-node head projections (x0.6), ping
__device__ float2 g_PB[NN];           // pong
__device__ int   g_csrc[ET + 16];     // CSR: src*8 (float2-P byte off; row=<<5)
__device__ int   g_rank[ET];          // per-edge rank within its dst (from hist)
__device__ int   g_rowptr[NN + 1];
__device__ int   g_cnt[NN];           // zero at entry (reset by layer2 epilogue)
__device__ int   g_agg[NCHUNK];       // decoupled-lookback state
__device__ int   g_inc[NCHUNK];
__device__ int   g_flag[NCHUNK];      // zeroed by k_hist each call
__device__ int   g_dcnt[NBIN];        // degree histogram (zeroed by k_hist)
__device__ int   g_doff[NBIN];
__device__ int   g_dcur[NBIN];
__device__ int   g_perm[NN];          // nodes sorted by degree bin (DESCENDING)

// ---------------------------------------------------------------------------
// CSR build (R11-exact)
// ---------------------------------------------------------------------------
__global__ void k_hist(const int* __restrict__ ei) {
    int e = blockIdx.x * blockDim.x + threadIdx.x;
    if (e < NCHUNK) g_flag[e] = 0;
    if (e < NBIN) g_dcnt[e] = 0;
    if (e >= ET) return;
    int dst = (e < NE) ? ei[NE + e] : (e - NE);
    g_rank[e] = atomicAdd(&g_cnt[dst], 1);    // rank = arrival order within dst
}

__global__ void __launch_bounds__(1024) k_scan() {
    __shared__ int s[1024];
    __shared__ int s_off;
    int c = blockIdx.x, tid = threadIdx.x;
    int i = c * 1024 + tid;
    int v = (i < NN) ? g_cnt[i] : 0;
    if (i < NN) atomicAdd(&g_dcnt[v < NBIN ? v : NBIN - 1], 1);   // degree bins
    s[tid] = v;
    __syncthreads();
    for (int off = 1; off < 1024; off <<= 1) {
        int t = (tid >= off) ? s[tid - off] : 0;
        __syncthreads();
        s[tid] += t;
        __syncthreads();
    }
    if (tid == 0) {
        int total = s[1023];
        g_agg[c] = total;
        __threadfence();
        atomicExch(&g_flag[c], 1);
        int off = 0;
        for (int j = c - 1; j >= 0;) {
            int f;
            do { f = atomicAdd(&g_flag[j], 0); } while (f == 0);
            if (f == 2) { off += atomicAdd(&g_inc[j], 0); break; }
            off += atomicAdd(&g_agg[j], 0);
            j--;
        }
        g_inc[c] = off + total;
        __threadfence();
        atomicExch(&g_flag[c], 2);
        s_off = off;
    }
    __syncthreads();
    if (i < NN) g_rowptr[i] = s_off + s[tid] - v;
    if (c == 0 && tid == 0) g_rowptr[NN] = ET;
}

// Bin offsets in DESCENDING degree order (heavy nodes first in g_perm).
__global__ void k_dscan() {       // 64 threads, 1 block
    __shared__ int s[NBIN];
    int t = threadIdx.x;
    int rt = NBIN - 1 - t;
    int v = g_dcnt[rt];
    s[t] = v;
    __syncthreads();
    for (int off = 1; off < NBIN; off <<= 1) {
        int u = (t >= off) ? s[t - off] : 0;
        __syncthreads();
        s[t] += u;
        __syncthreads();
    }
    g_doff[rt] = s[t] - v;
    g_dcur[rt] = 0;
}

__global__ void k_scatter(const int* __restrict__ ei) {
    int e = blockIdx.x * blockDim.x + threadIdx.x;
    if (e < NN) {                 // degree-binned permutation
        int deg = g_rowptr[e + 1] - g_rowptr[e];
        int b = deg < NBIN ? deg : NBIN - 1;
        int p = atomicAdd(&g_dcur[b], 1);
        g_perm[g_doff[b] + p] = e;
    }
    if (e >= ET) return;
    int src, dst;
    if (e < NE) { src = ei[e]; dst = ei[NE + e]; }
    else        { src = dst = e - NE; }
    g_csrc[g_rowptr[dst] + g_rank[e]] = src << 3;   // src*8 (P off; row = <<5)
}

// ---------------------------------------------------------------------------
// k_prep: P_h[n] = 0.6 * dot(att0_h, x_n) for layer 0. 16 lanes per node.
// ---------------------------------------------------------------------------
__global__ void __launch_bounds__(256) k_prep(
    const float* __restrict__ x, const float* __restrict__ att0)
{
    const unsigned FM = 0xffffffffu;
    int sub  = threadIdx.x >> 4;
    int lane = threadIdx.x & 15;
    int node = blockIdx.x * 16 + sub;
    float4 xv = ((const float4*)x)[node * 16 + lane];
    float4 a0 = ((const float4*)att0)[lane];
    float4 a1 = ((const float4*)(att0 + NC))[lane];
    float p0 = xv.x * a0.x + xv.y * a0.y + xv.z * a0.z + xv.w * a0.w;
    float p1 = xv.x * a1.x + xv.y * a1.y + xv.z * a1.z + xv.w * a1.w;
    p0 += __shfl_xor_sync(FM, p0, 1, 16);
    p1 += __shfl_xor_sync(FM, p1, 1, 16);
    float t = (lane & 1) ? p1 : p0;
    t += __shfl_xor_sync(FM, t, 2, 16);
    t += __shfl_xor_sync(FM, t, 4, 16);
    t += __shfl_xor_sync(FM, t, 8, 16);
    if (lane < 2) ((float*)&g_PA[node])[lane] = 0.6f * t;
}

// ---------------------------------------------------------------------------
// Fused GAT layer with linearized leaky-relu:
//   d_h = Pd_h + Ps_h + 0.4 * sum_c a_hc * |xd_c + xs_c|
// (P already x0.6). The |.| is a free FFMA operand modifier, so the per-edge
// channel cost is FADD + 2 FFMA. Plain softmax (logits O(1), no overflow).
// Per 2 edges: packed 12-shfl butterfly, ONE exp per lane, 4 broadcasts.
// Epilogue computes next layer's P from av (double-buffered PA/PB).
// ---------------------------------------------------------------------------
template<int LAYER>
__global__ void __launch_bounds__(256) k_layer(
    const float* __restrict__ h, float* __restrict__ hnext, float* __restrict__ acc,
    const float* __restrict__ attl, const float* __restrict__ biasl,
    const float* __restrict__ attn,     // next layer's att (unused for LAYER==2)
    const float2* __restrict__ Pc, float2* __restrict__ Pn)
{
    const unsigned FM = 0xffffffffu;
    int sub  = threadIdx.x >> 4;
    int lane = threadIdx.x & 15;
    int gi   = blockIdx.x * 16 + sub;          // grid*16 == NN exactly
    int node = g_perm[gi];                     // uniform across subgroup

    int start = g_rowptr[node];
    int deg   = g_rowptr[node + 1] - start;    // >= 1 (self loop)

    const char* hb = (const char*)h;
    const char* pb = (const char*)Pc;
    int lane16 = lane * 16;
    float4 xd = *(const float4*)(hb + (size_t)node * 256 + lane16);
    float4 a0 = ((const float4*)attl)[lane];
    float4 a1 = ((const float4*)(attl + NC))[lane];
    float2 pd2 = Pc[node];                     // 0.6*P of dst (uniform)
    float pdsel = (lane & 4) ? pd2.y : pd2.x;  // bit2 = head

    float sacc = 0.f;
    float4 c0 = make_float4(0.f, 0.f, 0.f, 0.f);
    float4 c1 = make_float4(0.f, 0.f, 0.f, 0.f);

    const int* cs = g_csrc + start;            // over-reads hit pad/neighbors
    int j0 = cs[0], j1 = cs[1];
    float4 xA = *(const float4*)(hb + (j0 << 5) + lane16);
    float4 xB = *(const float4*)(hb + (j1 << 5) + lane16);
    float2 psA = *(const float2*)(pb + j0);
    float2 psB = *(const float2*)(pb + j1);
    int j2 = cs[2], j3 = cs[3];

    for (int e = 0; e < deg; e += 2) {
        float4 nA = *(const float4*)(hb + (j2 << 5) + lane16);   // prefetch
        float4 nB = *(const float4*)(hb + (j3 << 5) + lane16);
        float2 npsA = *(const float2*)(pb + j2);
        float2 npsB = *(const float2*)(pb + j3);
        j2 = cs[e + 4]; j3 = cs[e + 5];

        // |u| dots (abs folds into FFMA operand modifiers)
        float vx, vy, vz, vw;
        vx = xd.x + xA.x; vy = xd.y + xA.y; vz = xd.z + xA.z; vw = xd.w + xA.w;
        float dA0 = fabsf(vx) * a0.x + fabsf(vy) * a0.y + fabsf(vz) * a0.z + fabsf(vw) * a0.w;
        float dA1 = fabsf(vx) * a1.x + fabsf(vy) * a1.y + fabsf(vz) * a1.z + fabsf(vw) * a1.w;
        vx = xd.x + xB.x; vy = xd.y + xB.y; vz = xd.z + xB.z; vw = xd.w + xB.w;
        float dB0 = fabsf(vx) * a0.x + fabsf(vy) * a0.y + fabsf(vz) * a0.z + fabsf(vw) * a0.w;
        float dB1 = fabsf(vx) * a1.x + fabsf(vy) * a1.y + fabsf(vz) * a1.z + fabsf(vw) * a1.w;

        // packed butterfly: 4 sums -> 1 per lane (bit3=edge, bit2=head)
        dA0 += __shfl_xor_sync(FM, dA0, 8, 16);
        dA1 += __shfl_xor_sync(FM, dA1, 8, 16);
        dB0 += __shfl_xor_sync(FM, dB0, 8, 16);
        dB1 += __shfl_xor_sync(FM, dB1, 8, 16);
        float u0 = (lane & 8) ? dB0 : dA0;
        float u1 = (lane & 8) ? dB1 : dA1;
        u0 += __shfl_xor_sync(FM, u0, 4, 16);
        u1 += __shfl_xor_sync(FM, u1, 4, 16);
        float w = (lane & 4) ? u1 : u0;
        w += __shfl_xor_sync(FM, w, 2, 16);
        w += __shfl_xor_sync(FM, w, 1, 16);
        // per-lane logit constant: Pd(head) + Ps(edge,head)
        float pssel = (lane & 8) ? ((lane & 4) ? psB.y : psB.x)
                                 : ((lane & 4) ? psA.y : psA.x);
        float ew = __expf(fmaf(w, 0.4f, pdsel + pssel));

        bool bval = (e + 1 < deg);
        sacc += (bval || lane < 8) ? ew : 0.f;

        float pA0 = __shfl_sync(FM, ew, 0, 16);
        float pA1 = __shfl_sync(FM, ew, 4, 16);
        float pB0 = __shfl_sync(FM, ew, 8, 16);
        float pB1 = __shfl_sync(FM, ew, 12, 16);
        if (!bval) { pB0 = 0.f; pB1 = 0.f; }

        c0.x += xA.x * pA0 + xB.x * pB0;  c0.y += xA.y * pA0 + xB.y * pB0;
        c0.z += xA.z * pA0 + xB.z * pB0;  c0.w += xA.w * pA0 + xB.w * pB0;
        c1.x += xA.x * pA1 + xB.x * pB1;  c1.y += xA.y * pA1 + xB.y * pB1;
        c1.z += xA.z * pA1 + xB.z * pB1;  c1.w += xA.w * pA1 + xB.w * pB1;

        xA = nA; xB = nB; psA = npsA; psB = npsB;
    }

    // finalize denominators (bit3 = edge, bit2 = head)
    float sO = sacc + __shfl_xor_sync(FM, sacc, 8, 16);
    float sX = __shfl_xor_sync(FM, sO, 4, 16);
    float s0 = (lane & 4) ? sX : sO;
    float s1 = (lane & 4) ? sO : sX;

    float i0 = 0.5f / (s0 + 1e-16f), i1 = 0.5f / (s1 + 1e-16f);
    float4 b = ((const float4*)biasl)[lane];
    float4 av;
    av.x = c0.x * i0 + c1.x * i1 + b.x;
    av.y = c0.y * i0 + c1.y * i1 + b.y;
    av.z = c0.z * i0 + c1.z * i1 + b.z;
    av.w = c0.w * i0 + c1.w * i1 + b.w;

    float4* ap = (float4*)acc + node * 16 + lane;
    if (LAYER == 0) {
        ((float4*)hnext)[node * 16 + lane] = av;
        float4 o; o.x = xd.x + av.x; o.y = xd.y + av.y; o.z = xd.z + av.z; o.w = xd.w + av.w;
        *ap = o;                               // acc = x + h1
    } else if (LAYER == 1) {
        ((float4*)hnext)[node * 16 + lane] = av;
        float4 o = *ap;
        o.x += av.x; o.y += av.y; o.z += av.z; o.w += av.w;
        *ap = o;
    } else {
        float4 o = *ap;                        // acc = (acc + h3) / 4
        o.x = (o.x + av.x) * 0.25f; o.y = (o.y + av.y) * 0.25f;
        o.z = (o.z + av.z) * 0.25f; o.w = (o.w + av.w) * 0.25f;
        *ap = o;
        int t = blockIdx.x * blockDim.x + threadIdx.x;
        if (t < NN) g_cnt[t] = 0;              // reset histogram for next replay
    }

    if (LAYER != 2) {
        // next layer's P from av: P_h = 0.6 * dot(attn_h, av)
        float4 an0 = ((const float4*)attn)[lane];
        float4 an1 = ((const float4*)(attn + NC))[lane];
        float p0 = av.x * an0.x + av.y * an0.y + av.z * an0.z + av.w * an0.w;
        float p1 = av.x * an1.x + av.y * an1.y + av.z * an1.z + av.w * an1.w;
        p0 += __shfl_xor_sync(FM, p0, 1, 16);
        p1 += __shfl_xor_sync(FM, p1, 1, 16);
        float t = (lane & 1) ? p1 : p0;
        t += __shfl_xor_sync(FM, t, 2, 16);
        t += __shfl_xor_sync(FM, t, 4, 16);
        t += __shfl_xor_sync(FM, t, 8, 16);
        if (lane < 2) ((float*)&Pn[node])[lane] = 0.6f * t;
    }
}

// ---------------------------------------------------------------------------
// Launch
// ---------------------------------------------------------------------------
extern "C" void kernel_launch(void* const* d_in, const int* in_sizes, int n_in,
                              void* d_out, int out_size) {
    const float* x    = (const float*)d_in[0];
    const int*   ei   = (const int*)d_in[1];
    const float* att  = (const float*)d_in[2];
    const float* bias = (const float*)d_in[3];
    float*       out  = (float*)d_out;

    float *hA, *hB;
    float2 *PA, *PB;
    cudaGetSymbolAddress((void**)&hA, g_hA);
    cudaGetSymbolAddress((void**)&hB, g_hB);
    cudaGetSymbolAddress((void**)&PA, g_PA);
    cudaGetSymbolAddress((void**)&PB, g_PB);

    const int gridE = (ET + 255) / 256;
    const int gridL = NN / 16;                 // 3125, exact

    k_hist<<<gridE, 256>>>(ei);
    k_scan<<<NCHUNK, 1024>>>();
    k_dscan<<<1, NBIN>>>();
    k_scatter<<<gridE, 256>>>(ei);
    k_prep<<<gridL, 256>>>(x, att);

    const float* a0 = att;
    const float* a1 = att + 2 * NC;
    const float* a2 = att + 4 * NC;
    k_layer<0><<<gridL, 256>>>(x,  hA, out, a0, bias + 0 * NC, a1, PA, PB);
    k_layer<1><<<gridL, 256>>>(hA, hB, out, a1, bias + 1 * NC, a2, PB, PA);
    k_layer<2><<<gridL, 256>>>(hB, hA, out, a2, bias + 2 * NC, a2, PA, PB);
}